// round 16
// baseline (speedup 1.0000x reference)
#include <cuda_runtime.h>
#include <cuda_bf16.h>

#define N_ 64
#define C_ 128
#define S_ 3600
#define K_ 64
#define NT 29              // tiles of 128 pixels
#define SPLIT 15           // 14 CTArows of 2 tiles + 1 of 1 tile
#define LDX 136            // bf16 row stride (272B)
#define LDL2 68            // fp32 logits row stride (16B-aligned rows)

// ---------------- static device scratch --------------------------------------
__device__ float g_d2part[(size_t)N_ * SPLIT * K_ * C_];   // [n][p][k][c]
__device__ float g_asump[N_ * SPLIT * K_];
__device__ float g_rowss[N_ * K_];

// ---------------- helpers -----------------------------------------------------
__device__ __forceinline__ unsigned smem_u32(const void* p) {
    unsigned a;
    asm("{ .reg .u64 t; cvta.to.shared.u64 t, %1; cvt.u32.u64 %0, t; }"
        : "=r"(a) : "l"(p));
    return a;
}
__device__ __forceinline__ void ldsm4t(unsigned addr, unsigned& r0, unsigned& r1,
                                       unsigned& r2, unsigned& r3) {
    asm volatile("ldmatrix.sync.aligned.m8n8.x4.trans.shared.b16 {%0,%1,%2,%3}, [%4];"
                 : "=r"(r0), "=r"(r1), "=r"(r2), "=r"(r3) : "r"(addr));
}
__device__ __forceinline__ void ldsm4(unsigned addr, unsigned& r0, unsigned& r1,
                                      unsigned& r2, unsigned& r3) {
    asm volatile("ldmatrix.sync.aligned.m8n8.x4.shared.b16 {%0,%1,%2,%3}, [%4];"
                 : "=r"(r0), "=r"(r1), "=r"(r2), "=r"(r3) : "r"(addr));
}
__device__ __forceinline__ void ldsm2(unsigned addr, unsigned& r0, unsigned& r1) {
    asm volatile("ldmatrix.sync.aligned.m8n8.x2.shared.b16 {%0,%1}, [%2];"
                 : "=r"(r0), "=r"(r1) : "r"(addr));
}
__device__ __forceinline__ void mma_bf16(float* d, const unsigned* a, const unsigned* b) {
    asm volatile("mma.sync.aligned.m16n8k16.row.col.f32.bf16.bf16.f32 "
                 "{%0,%1,%2,%3}, {%4,%5,%6,%7}, {%8,%9}, {%0,%1,%2,%3};"
                 : "+f"(d[0]), "+f"(d[1]), "+f"(d[2]), "+f"(d[3])
                 : "r"(a[0]), "r"(a[1]), "r"(a[2]), "r"(a[3]), "r"(b[0]), "r"(b[1]));
}
__device__ __forceinline__ unsigned pack4bf(float a, float b, float c, float d,
                                            unsigned& hi) {
    union { __nv_bfloat16 h[2]; unsigned u; } lo_u, hi_u;
    lo_u.h[0] = __float2bfloat16_rn(a); lo_u.h[1] = __float2bfloat16_rn(b);
    hi_u.h[0] = __float2bfloat16_rn(c); hi_u.h[1] = __float2bfloat16_rn(d);
    hi = hi_u.u;
    return lo_u.u;
}
// exp(x) on the FMA/ALU pipes (no MUFU). x <= 0 expected; rel err ~2e-6.
__device__ __forceinline__ float fexp(float x) {
    x = fmaxf(x, -60.0f);
    float t = fmaf(x, 1.44269504089f, 12582912.0f);   // 2^23*1.5 magic round
    int ei = __float_as_int(t) - 0x4B400000;          // integer part (signed)
    float i = t - 12582912.0f;
    float f = fmaf(x, 1.44269504089f, -i);            // frac in [-0.5,0.5]
    float p = 1.33335581e-3f;
    p = fmaf(p, f, 9.61812910e-3f);
    p = fmaf(p, f, 5.55041087e-2f);
    p = fmaf(p, f, 2.40226507e-1f);
    p = fmaf(p, f, 6.93147181e-1f);
    p = fmaf(p, f, 1.0f);                             // 2^f
    return __int_as_float(__float_as_int(p) + (ei << 23));
}

// ============================ kFA (fully fused) ===============================
// per 128-px tile: x->bf16, rnorm, logits HMMA, softmax (a' = a*rn), VLAD HMMA
#define XBF_OFF 0                        // 34816  [128 c][LDX s] bf16
#define WBF_OFF 34816                    // 17408  [64 k][LDX c]  bf16
#define LS_OFF  52224                    // 34816  [128 s][LDL2 k] fp32 logits
#define AST_OFF 87040                    // 17408  [64 k][LDX s]  bf16 a'
#define RN_OFF  104448                   // 512
#define NRM_OFF 104960                   // 512
#define ASR_OFF 105472                   // 1024
#define FA_BYTES 106496
__global__ void __launch_bounds__(256, 2) kFA(const float* __restrict__ x,
                                              const float* __restrict__ w) {
    extern __shared__ char smc[];
    __nv_bfloat16* xbf = (__nv_bfloat16*)(smc + XBF_OFF);
    __nv_bfloat16* wbf = (__nv_bfloat16*)(smc + WBF_OFF);
    float* ls  = (float*)(smc + LS_OFF);
    __nv_bfloat16* ast = (__nv_bfloat16*)(smc + AST_OFF);
    float* rn  = (float*)(smc + RN_OFF);
    float* nrm = (float*)(smc + NRM_OFF);
    float* asr = (float*)(smc + ASR_OFF);

    const int tid = threadIdx.x, lane = tid & 31, wid = tid >> 5;
    const int n = blockIdx.y, p = blockIdx.x;
    const int tbeg = 2 * p, tend = min(2 * p + 2, NT);

    const unsigned xb_u = smem_u32(xbf), wb_u = smem_u32(wbf), as_u = smem_u32(ast);
    const int msb = (wid & 3) * 32;    // s-block (HMMA1) / c-block (VLAD)
    const int ksb = (wid >> 2) * 32;   // k-block
    const int lb = lane >> 3, lr = lane & 7, lb2 = (lane >> 3) & 1;

    // --- load w once: [k][c] fp32 -> bf16 ---
    {
        const int k = tid >> 2, qq = tid & 3;
        const float* wr = w + k * C_;
        #pragma unroll
        for (int j = 0; j < 8; j++) {
            int c = qq * 32 + 4 * j;
            float4 v = *(const float4*)(wr + c);
            unsigned hi, lo = pack4bf(v.x, v.y, v.z, v.w, hi);
            *(uint2*)(wbf + k * LDX + c) = make_uint2(lo, hi);
        }
    }

    float acc2[2][4][4];          // VLAD accumulators [c][k], persist across tiles
    #pragma unroll
    for (int i = 0; i < 2; i++)
        #pragma unroll
        for (int j = 0; j < 4; j++)
            #pragma unroll
            for (int q = 0; q < 4; q++) acc2[i][j][q] = 0.f;
    float asumr = 0.f;
    const int kA = tid & 63, qA = tid >> 6;

    for (int t = tbeg; t < tend; t++) {
        const int s0 = t * 128;
        __syncthreads();   // prior tile reads done (and wbf visible on iter 0)

        // --- load x tile raw fp32 -> bf16 [c][s] ---
        {
            const int c = tid >> 1, h = tid & 1;
            const float* xr = x + ((size_t)n * C_ + c) * S_;
            #pragma unroll
            for (int q = 0; q < 16; q++) {
                int s = s0 + h * 64 + 4 * q;
                float4 v = make_float4(0.f, 0.f, 0.f, 0.f);
                if (s + 4 <= S_) v = *(const float4*)(xr + s);
                unsigned hi, lo = pack4bf(v.x, v.y, v.z, v.w, hi);
                *(uint2*)(xbf + c * LDX + h * 64 + 4 * q) = make_uint2(lo, hi);
            }
        }
        __syncthreads();

        // --- rnorm: 4 threads per pixel-pair, packed uint LDS.32 ---
        {
            const int jp = tid >> 2, q = tid & 3;     // pixel pair {2jp, 2jp+1}
            const unsigned* xw = (const unsigned*)xbf;
            float ss0 = 0.f, ss1 = 0.f;
            #pragma unroll 8
            for (int i = 0; i < 32; i++) {
                int c = 32 * q + ((i + q) & 31);      // q-stagger for banks
                unsigned u = xw[c * (LDX / 2) + jp];
                float lo = __int_as_float(u << 16);
                float hi = __int_as_float(u & 0xFFFF0000u);
                ss0 = fmaf(lo, lo, ss0);
                ss1 = fmaf(hi, hi, ss1);
            }
            ss0 += __shfl_xor_sync(0xffffffffu, ss0, 1);
            ss0 += __shfl_xor_sync(0xffffffffu, ss0, 2);
            ss1 += __shfl_xor_sync(0xffffffffu, ss1, 1);
            ss1 += __shfl_xor_sync(0xffffffffu, ss1, 2);
            if (q == 0) {
                int s_a = 2 * jp, s_b = 2 * jp + 1;
                float na = fmaxf(sqrtf(ss0), 1e-12f);
                float nb = fmaxf(sqrtf(ss1), 1e-12f);
                bool va = (s0 + s_a) < S_, vb = (s0 + s_b) < S_;
                rn[s_a]  = va ? (1.0f / na) : 0.f;
                nrm[s_a] = va ? na : 0.f;
                rn[s_b]  = vb ? (1.0f / nb) : 0.f;
                nrm[s_b] = vb ? nb : 0.f;
            }
        }

        // --- HMMA1: l0[s][k] = x[s][c] . w[k][c]; store fp32 -> ls[s][k] ---
        {
            float la[2][4][4];
            #pragma unroll
            for (int i = 0; i < 2; i++)
                #pragma unroll
                for (int j = 0; j < 4; j++)
                    #pragma unroll
                    for (int q = 0; q < 4; q++) la[i][j][q] = 0.f;
            #pragma unroll
            for (int kc = 0; kc < 8; kc++) {
                const int c0 = kc * 16;
                unsigned af[2][4], bfr[4][2];
                #pragma unroll
                for (int mt = 0; mt < 2; mt++) {
                    unsigned addr = xb_u +
                        ((unsigned)((c0 + ((lb & 2) ? 8 : 0) + lr) * LDX +
                                    (msb + 16 * mt) + ((lb & 1) ? 8 : 0)) << 1);
                    ldsm4t(addr, af[mt][0], af[mt][1], af[mt][2], af[mt][3]);
                }
                #pragma unroll
                for (int nt = 0; nt < 4; nt++) {
                    unsigned addr = wb_u +
                        ((unsigned)((ksb + 8 * nt + lr) * LDX + c0 + lb2 * 8) << 1);
                    ldsm2(addr, bfr[nt][0], bfr[nt][1]);
                }
                #pragma unroll
                for (int mt = 0; mt < 2; mt++)
                    #pragma unroll
                    for (int nt = 0; nt < 4; nt++) mma_bf16(la[mt][nt], af[mt], bfr[nt]);
            }
            #pragma unroll
            for (int mt = 0; mt < 2; mt++)
                #pragma unroll
                for (int nt = 0; nt < 4; nt++) {
                    int row = msb + 16 * mt + (lane >> 2);
                    int col = ksb + 8 * nt + 2 * (lane & 3);
                    *(float2*)(ls + row * LDL2 + col) =
                        make_float2(la[mt][nt][0], la[mt][nt][1]);
                    *(float2*)(ls + (row + 8) * LDL2 + col) =
                        make_float2(la[mt][nt][2], la[mt][nt][3]);
                }
        }
        __syncthreads();

        // --- softmax per pixel (vectorized ls reads); a' = a*rn -> ast[k][s] ---
        {
            const int s = tid >> 1, h = tid & 1;
            const float r = rn[s];
            float lv[32];
            const float4* lsr = (const float4*)(ls + s * LDL2 + 32 * h);
            #pragma unroll
            for (int j = 0; j < 8; j++) {
                float4 v = lsr[j];
                lv[4 * j]     = v.x * r;
                lv[4 * j + 1] = v.y * r;
                lv[4 * j + 2] = v.z * r;
                lv[4 * j + 3] = v.w * r;
            }
            float m = lv[0];
            #pragma unroll
            for (int j = 1; j < 32; j++) m = fmaxf(m, lv[j]);
            m = fmaxf(m, __shfl_xor_sync(0xffffffffu, m, 1));
            float sum = 0.f;
            #pragma unroll
            for (int j = 0; j < 32; j++) {
                lv[j] = fexp(lv[j] - m);
                sum += lv[j];
            }
            sum += __shfl_xor_sync(0xffffffffu, sum, 1);
            float sc = r / sum;      // folds rn into a; 0 for padded pixels
            #pragma unroll
            for (int j = 0; j < 32; j++) {
                int jj = (j + 4 * h) & 31;   // stagger rows between half-threads
                ast[(32 * h + jj) * LDX + s] = __float2bfloat16_rn(lv[jj] * sc);
            }
        }
        __syncthreads();

        // --- asum accumulate: asum[k] += sum_s a'[k][s] * nrm[s] ---
        #pragma unroll 8
        for (int u = 0; u < 32; u++) {
            int s = qA * 32 + u;
            asumr = fmaf(__bfloat162float(ast[kA * LDX + s]), nrm[s], asumr);
        }

        // --- VLAD HMMA: acc2[c][k] += x_raw[c][s] . a'[k][s] ---
        #pragma unroll
        for (int ks = 0; ks < 8; ks++) {
            const int sst = ks * 16;
            unsigned af[2][4], bfr[4][2];
            #pragma unroll
            for (int mt = 0; mt < 2; mt++) {
                unsigned addr = xb_u +
                    ((unsigned)((msb + 16 * mt + (lb & 1) * 8 + lr) * LDX +
                                sst + ((lb & 2) ? 8 : 0)) << 1);
                ldsm4(addr, af[mt][0], af[mt][1], af[mt][2], af[mt][3]);
            }
            #pragma unroll
            for (int nt = 0; nt < 4; nt++) {
                unsigned addr = as_u +
                    ((unsigned)((ksb + 8 * nt + lr) * LDX + sst + lb2 * 8) << 1);
                ldsm2(addr, bfr[nt][0], bfr[nt][1]);
            }
            #pragma unroll
            for (int mt = 0; mt < 2; mt++)
                #pragma unroll
                for (int nt = 0; nt < 4; nt++) mma_bf16(acc2[mt][nt], af[mt], bfr[nt]);
        }
    }

    // --- asum partials out ---
    asr[tid] = asumr;
    __syncthreads();           // also: all VLAD reads of xbf done -> safe to reuse
    if (tid < 64)
        g_asump[(n * SPLIT + p) * K_ + tid] =
            asr[tid] + asr[tid + 64] + asr[tid + 128] + asr[tid + 192];

    // --- transpose acc2 to [k][c] via smem (reuse xbf region), store coalesced ---
    float* vo = (float*)(smc + XBF_OFF);   // [64 k][132]
    #pragma unroll
    for (int mt = 0; mt < 2; mt++)
        #pragma unroll
        for (int nt = 0; nt < 4; nt++) {
            int c_r = msb + 16 * mt + (lane >> 2);
            int k_c = ksb + 8 * nt + 2 * (lane & 3);
            vo[k_c * 132 + c_r]           = acc2[mt][nt][0];
            vo[(k_c + 1) * 132 + c_r]     = acc2[mt][nt][1];
            vo[k_c * 132 + c_r + 8]       = acc2[mt][nt][2];
            vo[(k_c + 1) * 132 + c_r + 8] = acc2[mt][nt][3];
        }
    __syncthreads();
    float* dst = g_d2part + (size_t)(n * SPLIT + p) * K_ * C_;
    for (int i = tid; i < K_ * 32; i += 256) {
        int k = i >> 5, g = i & 31;
        *(float4*)(dst + k * C_ + 4 * g) = *(const float4*)(vo + k * 132 + 4 * g);
    }
}

// ============================ kC1 =============================================
// per (n,k): reduce 15 partials (MLP=15, coalesced), centroid subtract,
// row normalize, store row + row sumsq
__global__ __launch_bounds__(128) void kC1(const float* __restrict__ cent,
                                           float* __restrict__ out) {
    const int n = blockIdx.y, k = blockIdx.x, c = threadIdx.x;

    float asum = 0.f;
    #pragma unroll
    for (int p = 0; p < SPLIT; p++)
        asum += g_asump[(n * SPLIT + p) * K_ + k];

    float v = 0.f;
    #pragma unroll
    for (int p = 0; p < SPLIT; p++)
        v += g_d2part[(size_t)(n * SPLIT + p) * K_ * C_ + k * C_ + c];
    v -= asum * cent[k * C_ + c];

    float ss = v * v;
    #pragma unroll
    for (int o = 16; o; o >>= 1) ss += __shfl_xor_sync(0xffffffffu, ss, o);
    __shared__ float sred[4];
    if ((c & 31) == 0) sred[c >> 5] = ss;
    __syncthreads();
    float tot = sred[0] + sred[1] + sred[2] + sred[3];
    float d = fmaxf(sqrtf(tot), 1e-12f);
    out[((size_t)n * K_ + k) * C_ + c] = v / d;
    if (c == 0) g_rowss[n * K_ + k] = tot / (d * d);
}

// ============================ kC2 =============================================
__global__ __launch_bounds__(256) void kC2(float* __restrict__ out) {
    const int n = blockIdx.x, tid = threadIdx.x;
    __shared__ float sred[2];
    if (tid < 64) {
        float ss = g_rowss[n * 64 + tid];
        #pragma unroll
        for (int o = 16; o; o >>= 1) ss += __shfl_xor_sync(0xffffffffu, ss, o);
        if ((tid & 31) == 0) sred[tid >> 5] = ss;
    }
    __syncthreads();
    float d = fmaxf(sqrtf(sred[0] + sred[1]), 1e-12f);
    float r = 1.0f / d;
    float4* o = (float4*)(out + (size_t)n * K_ * C_);
    for (int i = tid; i < K_ * C_ / 4; i += 256) {
        float4 v = o[i];
        o[i] = make_float4(v.x * r, v.y * r, v.z * r, v.w * r);
    }
}

// ============================ launch =========================================
extern "C" void kernel_launch(void* const* d_in, const int* in_sizes, int n_in,
                              void* d_out, int out_size) {
    const float* x    = (const float*)d_in[0];
    const float* w    = (const float*)d_in[1];
    const float* cent = (const float*)d_in[2];
    float* out = (float*)d_out;

    cudaFuncSetAttribute(kFA, cudaFuncAttributeMaxDynamicSharedMemorySize, FA_BYTES);

    kFA<<<dim3(SPLIT, N_), 256, FA_BYTES>>>(x, w);
    kC1<<<dim3(K_, N_), 128>>>(cent, out);
    kC2<<<N_, 256>>>(out);
}

// round 17
// speedup vs baseline: 1.1963x; 1.1963x over previous
#include <cuda_runtime.h>
#include <cuda_bf16.h>

#define N_ 64
#define C_ 128
#define S_ 3600
#define K_ 64
#define NT 29              // tiles of 128 pixels
#define SPLIT 15           // 14 CTArows of 2 tiles + 1 of 1 tile
#define LDX 136            // bf16 row stride (272B)

// ---------------- static device scratch --------------------------------------
__device__ float g_d2part[(size_t)N_ * SPLIT * K_ * C_];   // [n][p][k][c]
__device__ float g_asump[N_ * SPLIT * K_];
__device__ float g_rowss[N_ * K_];

// ---------------- helpers -----------------------------------------------------
__device__ __forceinline__ unsigned smem_u32(const void* p) {
    unsigned a;
    asm("{ .reg .u64 t; cvta.to.shared.u64 t, %1; cvt.u32.u64 %0, t; }"
        : "=r"(a) : "l"(p));
    return a;
}
__device__ __forceinline__ void ldsm4t(unsigned addr, unsigned& r0, unsigned& r1,
                                       unsigned& r2, unsigned& r3) {
    asm volatile("ldmatrix.sync.aligned.m8n8.x4.trans.shared.b16 {%0,%1,%2,%3}, [%4];"
                 : "=r"(r0), "=r"(r1), "=r"(r2), "=r"(r3) : "r"(addr));
}
__device__ __forceinline__ void ldsm4(unsigned addr, unsigned& r0, unsigned& r1,
                                      unsigned& r2, unsigned& r3) {
    asm volatile("ldmatrix.sync.aligned.m8n8.x4.shared.b16 {%0,%1,%2,%3}, [%4];"
                 : "=r"(r0), "=r"(r1), "=r"(r2), "=r"(r3) : "r"(addr));
}
__device__ __forceinline__ void ldsm2(unsigned addr, unsigned& r0, unsigned& r1) {
    asm volatile("ldmatrix.sync.aligned.m8n8.x2.shared.b16 {%0,%1}, [%2];"
                 : "=r"(r0), "=r"(r1) : "r"(addr));
}
__device__ __forceinline__ void mma_bf16(float* d, const unsigned* a, const unsigned* b) {
    asm volatile("mma.sync.aligned.m16n8k16.row.col.f32.bf16.bf16.f32 "
                 "{%0,%1,%2,%3}, {%4,%5,%6,%7}, {%8,%9}, {%0,%1,%2,%3};"
                 : "+f"(d[0]), "+f"(d[1]), "+f"(d[2]), "+f"(d[3])
                 : "r"(a[0]), "r"(a[1]), "r"(a[2]), "r"(a[3]), "r"(b[0]), "r"(b[1]));
}
__device__ __forceinline__ unsigned pack4bf(float a, float b, float c, float d,
                                            unsigned& hi) {
    union { __nv_bfloat16 h[2]; unsigned u; } lo_u, hi_u;
    lo_u.h[0] = __float2bfloat16_rn(a); lo_u.h[1] = __float2bfloat16_rn(b);
    hi_u.h[0] = __float2bfloat16_rn(c); hi_u.h[1] = __float2bfloat16_rn(d);
    hi = hi_u.u;
    return lo_u.u;
}
// exp(x) on the FMA/ALU pipes (no MUFU). x <= 0 expected; rel err ~2e-6.
__device__ __forceinline__ float fexp(float x) {
    x = fmaxf(x, -60.0f);
    float t = fmaf(x, 1.44269504089f, 12582912.0f);   // 2^23*1.5 magic round
    int ei = __float_as_int(t) - 0x4B400000;          // integer part (signed)
    float i = t - 12582912.0f;
    float f = fmaf(x, 1.44269504089f, -i);            // frac in [-0.5,0.5]
    float p = 1.33335581e-3f;
    p = fmaf(p, f, 9.61812910e-3f);
    p = fmaf(p, f, 5.55041087e-2f);
    p = fmaf(p, f, 2.40226507e-1f);
    p = fmaf(p, f, 6.93147181e-1f);
    p = fmaf(p, f, 1.0f);                             // 2^f
    return __int_as_float(__float_as_int(p) + (ei << 23));
}

// ============================ kFA (fully fused) ===============================
// per 128-px tile: x->bf16, rnorm, logits HMMA, softmax (a' = a*rn), VLAD HMMA
#define XBF_OFF 0
#define WBF_OFF 34816
#define AST_OFF 52224
#define RN_OFF  69632
#define NRM_OFF 70144
#define ASR_OFF 70656
#define FA_BYTES 71680
__global__ void __launch_bounds__(256, 2) kFA(const float* __restrict__ x,
                                              const float* __restrict__ w) {
    extern __shared__ char smc[];
    __nv_bfloat16* xbf = (__nv_bfloat16*)(smc + XBF_OFF);  // [128 c][LDX s] raw x
    __nv_bfloat16* wbf = (__nv_bfloat16*)(smc + WBF_OFF);  // [64 k][LDX c]
    __nv_bfloat16* ast = (__nv_bfloat16*)(smc + AST_OFF);  // [64 k][LDX s] logits->a'
    float* rn  = (float*)(smc + RN_OFF);                   // 1/max(||x||,eps) (0 if pad)
    float* nrm = (float*)(smc + NRM_OFF);                  // max(||x||,eps)   (0 if pad)
    float* asr = (float*)(smc + ASR_OFF);                  // asum reduce [256]

    const int tid = threadIdx.x, lane = tid & 31, wid = tid >> 5;
    const int n = blockIdx.y, p = blockIdx.x;
    const int tbeg = 2 * p, tend = min(2 * p + 2, NT);

    const unsigned xb_u = smem_u32(xbf), wb_u = smem_u32(wbf), as_u = smem_u32(ast);
    const int msb = (wid & 3) * 32;    // s-block (HMMA1) / c-block (VLAD)
    const int ksb = (wid >> 2) * 32;   // k-block
    const int lb = lane >> 3, lr = lane & 7, lb2 = (lane >> 3) & 1;

    // --- load w once: [k][c] fp32 -> bf16 ---
    {
        const int k = tid >> 2, qq = tid & 3;
        const float* wr = w + k * C_;
        #pragma unroll
        for (int j = 0; j < 8; j++) {
            int c = qq * 32 + 4 * j;
            float4 v = *(const float4*)(wr + c);
            unsigned hi, lo = pack4bf(v.x, v.y, v.z, v.w, hi);
            *(uint2*)(wbf + k * LDX + c) = make_uint2(lo, hi);
        }
    }

    float acc2[2][4][4];          // VLAD accumulators [c][k], persist across tiles
    #pragma unroll
    for (int i = 0; i < 2; i++)
        #pragma unroll
        for (int j = 0; j < 4; j++)
            #pragma unroll
            for (int q = 0; q < 4; q++) acc2[i][j][q] = 0.f;
    float asumr = 0.f;
    const int kA = tid & 63, qA = tid >> 6;

    for (int t = tbeg; t < tend; t++) {
        const int s0 = t * 128;
        __syncthreads();   // prior tile reads done (and wbf visible on iter 0)

        // --- load x tile raw fp32 -> bf16 [c][s] ---
        {
            const int c = tid >> 1, h = tid & 1;
            const float* xr = x + ((size_t)n * C_ + c) * S_;
            #pragma unroll
            for (int q = 0; q < 16; q++) {
                int s = s0 + h * 64 + 4 * q;
                float4 v = make_float4(0.f, 0.f, 0.f, 0.f);
                if (s + 4 <= S_) v = *(const float4*)(xr + s);
                unsigned hi, lo = pack4bf(v.x, v.y, v.z, v.w, hi);
                *(uint2*)(xbf + c * LDX + h * 64 + 4 * q) = make_uint2(lo, hi);
            }
        }
        __syncthreads();

        // --- rnorm (2 threads/pixel, staggered banks) ---
        {
            const int s = tid >> 1, h = tid & 1;
            float ss = 0.f;
            #pragma unroll 8
            for (int cc = 0; cc < 64; cc++) {
                int c = 64 * h + ((cc + 4 * h) & 63);
                float v = __bfloat162float(xbf[c * LDX + s]);
                ss = fmaf(v, v, ss);
            }
            ss += __shfl_xor_sync(0xffffffffu, ss, 1);
            if (h == 0) {
                bool valid = (s0 + s) < S_;
                float nm = fmaxf(sqrtf(ss), 1e-12f);
                rn[s]  = valid ? (1.0f / nm) : 0.f;
                nrm[s] = valid ? nm : 0.f;
            }
        }

        // --- HMMA1: l0[s][k] = x[s][c] . w[k][c]; store bf16 -> ast[k][s] ---
        {
            float la[2][4][4];
            #pragma unroll
            for (int i = 0; i < 2; i++)
                #pragma unroll
                for (int j = 0; j < 4; j++)
                    #pragma unroll
                    for (int q = 0; q < 4; q++) la[i][j][q] = 0.f;
            #pragma unroll
            for (int kc = 0; kc < 8; kc++) {
                const int c0 = kc * 16;
                unsigned af[2][4], bfr[4][2];
                #pragma unroll
                for (int mt = 0; mt < 2; mt++) {
                    unsigned addr = xb_u +
                        ((unsigned)((c0 + ((lb & 2) ? 8 : 0) + lr) * LDX +
                                    (msb + 16 * mt) + ((lb & 1) ? 8 : 0)) << 1);
                    ldsm4t(addr, af[mt][0], af[mt][1], af[mt][2], af[mt][3]);
                }
                #pragma unroll
                for (int nt = 0; nt < 4; nt++) {
                    unsigned addr = wb_u +
                        ((unsigned)((ksb + 8 * nt + lr) * LDX + c0 + lb2 * 8) << 1);
                    ldsm2(addr, bfr[nt][0], bfr[nt][1]);
                }
                #pragma unroll
                for (int mt = 0; mt < 2; mt++)
                    #pragma unroll
                    for (int nt = 0; nt < 4; nt++) mma_bf16(la[mt][nt], af[mt], bfr[nt]);
            }
            #pragma unroll
            for (int mt = 0; mt < 2; mt++)
                #pragma unroll
                for (int nt = 0; nt < 4; nt++) {
                    int row = msb + 16 * mt + (lane >> 2);
                    int col = ksb + 8 * nt + 2 * (lane & 3);
                    ast[col * LDX + row]           = __float2bfloat16_rn(la[mt][nt][0]);
                    ast[(col + 1) * LDX + row]     = __float2bfloat16_rn(la[mt][nt][1]);
                    ast[col * LDX + row + 8]       = __float2bfloat16_rn(la[mt][nt][2]);
                    ast[(col + 1) * LDX + row + 8] = __float2bfloat16_rn(la[mt][nt][3]);
                }
        }
        __syncthreads();

        // --- softmax per pixel; write a' = a * rn[s] back into ast ---
        {
            const int s = tid >> 1, h = tid & 1;
            const float r = rn[s];
            float lv[32];
            #pragma unroll
            for (int j = 0; j < 32; j++) {
                int k = 32 * h + ((j + 4 * h) & 31);
                lv[j] = __bfloat162float(ast[k * LDX + s]) * r;
            }
            float m = lv[0];
            #pragma unroll
            for (int j = 1; j < 32; j++) m = fmaxf(m, lv[j]);
            m = fmaxf(m, __shfl_xor_sync(0xffffffffu, m, 1));
            float sum = 0.f;
            #pragma unroll
            for (int j = 0; j < 32; j++) {
                lv[j] = fexp(lv[j] - m);
                sum += lv[j];
            }
            sum += __shfl_xor_sync(0xffffffffu, sum, 1);
            float sc = r / sum;      // folds rn into a; 0 for padded pixels
            #pragma unroll
            for (int j = 0; j < 32; j++) {
                int k = 32 * h + ((j + 4 * h) & 31);
                ast[k * LDX + s] = __float2bfloat16_rn(lv[j] * sc);
            }
        }
        __syncthreads();

        // --- asum accumulate: asum[k] += sum_s a'[k][s] * nrm[s] ---
        // kA-staggered s order: reduces 4-way bank conflicts on ast reads
        #pragma unroll 8
        for (int u = 0; u < 32; u++) {
            int s = qA * 32 + ((u + kA) & 31);
            asumr = fmaf(__bfloat162float(ast[kA * LDX + s]), nrm[s], asumr);
        }

        // --- VLAD HMMA: acc2[c][k] += x_raw[c][s] . a'[k][s] ---
        #pragma unroll
        for (int ks = 0; ks < 8; ks++) {
            const int sst = ks * 16;
            unsigned af[2][4], bfr[4][2];
            #pragma unroll
            for (int mt = 0; mt < 2; mt++) {
                unsigned addr = xb_u +
                    ((unsigned)((msb + 16 * mt + (lb & 1) * 8 + lr) * LDX +
                                sst + ((lb & 2) ? 8 : 0)) << 1);
                ldsm4(addr, af[mt][0], af[mt][1], af[mt][2], af[mt][3]);
            }
            #pragma unroll
            for (int nt = 0; nt < 4; nt++) {
                unsigned addr = as_u +
                    ((unsigned)((ksb + 8 * nt + lr) * LDX + sst + lb2 * 8) << 1);
                ldsm2(addr, bfr[nt][0], bfr[nt][1]);
            }
            #pragma unroll
            for (int mt = 0; mt < 2; mt++)
                #pragma unroll
                for (int nt = 0; nt < 4; nt++) mma_bf16(acc2[mt][nt], af[mt], bfr[nt]);
        }
    }

    // --- asum partials out ---
    asr[tid] = asumr;
    __syncthreads();           // also: all VLAD reads of xbf done -> safe to reuse
    if (tid < 64)
        g_asump[(n * SPLIT + p) * K_ + tid] =
            asr[tid] + asr[tid + 64] + asr[tid + 128] + asr[tid + 192];

    // --- transpose acc2 to [k][c] via smem (reuse xbf region), store coalesced ---
    float* vo = (float*)(smc + XBF_OFF);   // [64 k][132]
    #pragma unroll
    for (int mt = 0; mt < 2; mt++)
        #pragma unroll
        for (int nt = 0; nt < 4; nt++) {
            int c_r = msb + 16 * mt + (lane >> 2);
            int k_c = ksb + 8 * nt + 2 * (lane & 3);
            vo[k_c * 132 + c_r]           = acc2[mt][nt][0];
            vo[(k_c + 1) * 132 + c_r]     = acc2[mt][nt][1];
            vo[k_c * 132 + c_r + 8]       = acc2[mt][nt][2];
            vo[(k_c + 1) * 132 + c_r + 8] = acc2[mt][nt][3];
        }
    __syncthreads();
    float* dst = g_d2part + (size_t)(n * SPLIT + p) * K_ * C_;
    for (int i = tid; i < K_ * 32; i += 256) {
        int k = i >> 5, g = i & 31;
        *(float4*)(dst + k * C_ + 4 * g) = *(const float4*)(vo + k * 132 + 4 * g);
    }
}

// ============================ kC1 =============================================
// per (n,k): reduce 15 partials (MLP=15, coalesced), centroid subtract,
// row normalize, store row + row sumsq
__global__ __launch_bounds__(128) void kC1(const float* __restrict__ cent,
                                           float* __restrict__ out) {
    const int n = blockIdx.y, k = blockIdx.x, c = threadIdx.x;

    float asum = 0.f;
    #pragma unroll
    for (int p = 0; p < SPLIT; p++)
        asum += g_asump[(n * SPLIT + p) * K_ + k];

    float v = 0.f;
    #pragma unroll
    for (int p = 0; p < SPLIT; p++)
        v += g_d2part[(size_t)(n * SPLIT + p) * K_ * C_ + k * C_ + c];
    v -= asum * cent[k * C_ + c];

    float ss = v * v;
    #pragma unroll
    for (int o = 16; o; o >>= 1) ss += __shfl_xor_sync(0xffffffffu, ss, o);
    __shared__ float sred[4];
    if ((c & 31) == 0) sred[c >> 5] = ss;
    __syncthreads();
    float tot = sred[0] + sred[1] + sred[2] + sred[3];
    float d = fmaxf(sqrtf(tot), 1e-12f);
    out[((size_t)n * K_ + k) * C_ + c] = v / d;
    if (c == 0) g_rowss[n * K_ + k] = tot / (d * d);
}

// ============================ kC2 =============================================
__global__ __launch_bounds__(256) void kC2(float* __restrict__ out) {
    const int n = blockIdx.x, tid = threadIdx.x;
    __shared__ float sred[2];
    if (tid < 64) {
        float ss = g_rowss[n * 64 + tid];
        #pragma unroll
        for (int o = 16; o; o >>= 1) ss += __shfl_xor_sync(0xffffffffu, ss, o);
        if ((tid & 31) == 0) sred[tid >> 5] = ss;
    }
    __syncthreads();
    float d = fmaxf(sqrtf(sred[0] + sred[1]), 1e-12f);
    float r = 1.0f / d;
    float4* o = (float4*)(out + (size_t)n * K_ * C_);
    for (int i = tid; i < K_ * C_ / 4; i += 256) {
        float4 v = o[i];
        o[i] = make_float4(v.x * r, v.y * r, v.z * r, v.w * r);
    }
}

// ============================ launch =========================================
extern "C" void kernel_launch(void* const* d_in, const int* in_sizes, int n_in,
                              void* d_out, int out_size) {
    const float* x    = (const float*)d_in[0];
    const float* w    = (const float*)d_in[1];
    const float* cent = (const float*)d_in[2];
    float* out = (float*)d_out;

    cudaFuncSetAttribute(kFA, cudaFuncAttributeMaxDynamicSharedMemorySize, FA_BYTES);

    kFA<<<dim3(SPLIT, N_), 256, FA_BYTES>>>(x, w);
    kC1<<<dim3(K_, N_), 128>>>(cent, out);
    kC2<<<N_, 256>>>(out);
}